// round 5
// baseline (speedup 1.0000x reference)
#include <cuda_runtime.h>

#define NTOT 200      // histogram bins
#define TILE 256      // tile side (A rows and B cols per block)
#define BLKT 128      // threads per block (each thread owns 2 A rows)
#define NWARP 4
#define NBUCK 256     // x-sort buckets
#define MAXPTS 16384

// Sorted & prescaled points: (x,y,z)*real_size*20, w=|p|^2. pos0 at [0,n0),
// pos1 at [n0, n0+n1).
__device__ float4 g_pts[MAXPTS];
// 3 raw integer histograms: [0]=00-tri, [1]=01-cross, [2]=11-tri.
// finalize_kernel re-zeroes after reading so graph replays start clean.
__device__ int g_hist[3 * NTOT];

__device__ __forceinline__ float fsqrt_approx(float x) {
    float r;
    asm("sqrt.approx.f32 %0, %1;" : "=f"(r) : "f"(x));
    return r;
}

// Counting sort by x-bucket; block 0 handles pos0, block 1 handles pos1.
// Output is bucket-ordered (within-bucket order is race-dependent, which is
// fine: the histogram is a permutation-invariant integer reduction).
__global__ __launch_bounds__(NBUCK) void sort_kernel(
    const float* __restrict__ pos0, const float* __restrict__ pos1,
    const float* __restrict__ rs, int n0, int n1)
{
    __shared__ int cnt[NBUCK];
    __shared__ int offs[NBUCK];
    const float* p = blockIdx.x ? pos1 : pos0;
    const int n    = blockIdx.x ? n1 : n0;
    const int base = blockIdx.x ? n0 : 0;
    const int tid  = threadIdx.x;

    const float r0 = rs[0] * 20.0f, r1 = rs[1] * 20.0f, r2 = rs[2] * 20.0f;

    cnt[tid] = 0;
    __syncthreads();
    for (int i = tid; i < n; i += NBUCK) {
        int b = (int)(p[3 * i] * (float)NBUCK);
        b = max(0, min(NBUCK - 1, b));
        atomicAdd(&cnt[b], 1);
    }
    __syncthreads();
    int own = cnt[tid];
    // inclusive Hillis-Steele scan
    for (int d = 1; d < NBUCK; d <<= 1) {
        int t = (tid >= d) ? cnt[tid - d] : 0;
        __syncthreads();
        cnt[tid] += t;
        __syncthreads();
    }
    offs[tid] = cnt[tid] - own;   // exclusive start = running cursor
    __syncthreads();
    for (int i = tid; i < n; i += NBUCK) {
        float x = p[3 * i + 0];
        float y = p[3 * i + 1];
        float z = p[3 * i + 2];
        int b = (int)(x * (float)NBUCK);
        b = max(0, min(NBUCK - 1, b));
        int pos = atomicAdd(&offs[b], 1);
        float sx = x * r0, sy = y * r1, sz = z * r2;
        float q = sx * sx; q = fmaf(sy, sy, q); q = fmaf(sz, sz, q);
        g_pts[base + pos] = make_float4(sx, sy, sz, q);
    }
}

// Invert upper-triangle linear index t -> (bi, bj), bj >= bi.
__device__ __forceinline__ void tri_decode(int t, int n, int& bi, int& bj) {
    float fn = (float)(2 * n + 1);
    int b = (int)((fn - sqrtf(fmaxf(fn * fn - 8.0f * (float)t, 0.0f))) * 0.5f);
    if (b < 0) b = 0;
    if (b > n - 1) b = n - 1;
    while (b > 0 && t < b * (2 * n - b + 1) / 2) b--;
    while (b < n - 1 && t >= (b + 1) * (2 * n - b) / 2) b++;
    bi = b;
    bj = b + (t - b * (2 * n - b + 1) / 2);
}

__global__ __launch_bounds__(BLKT) void pair_fused_kernel(
    int n0, int n1, int nb0, int nb1, int T0, int C)
{
    __shared__ float4 sB[TILE];
    __shared__ int    sh[NWARP * NTOT];

    // ---- decode block -> work unit ----
    int w = blockIdx.x;
    int bi, bj, aOff, bOff, nA, nB, histIdx;
    bool diag;
    if (w < T0) {                     // 0-0 triangle
        tri_decode(w, nb0, bi, bj);
        aOff = 0; bOff = 0; nA = n0; nB = n0; histIdx = 0;
        diag = (bi == bj);
    } else if (w < T0 + C) {          // 0-1 cross
        int u = w - T0;
        bi = u / nb1; bj = u - bi * nb1;
        aOff = 0; nA = n0; bOff = n0; nB = n1; histIdx = 1;
        diag = false;
    } else {                          // 1-1 triangle
        int u = w - T0 - C;
        tri_decode(u, nb1, bi, bj);
        aOff = n0; bOff = n0; nA = n1; nB = n1; histIdx = 2;
        diag = (bi == bj);
    }
    const int rowStart  = bi * TILE;
    const int chunkBase = bj * TILE;

    // ---- x-gap cull (points sorted by x). Bucket width = 500/256 < 2 scaled
    // units; endpoints are bucket-accurate, so pad threshold 200 -> 205.
    {
        float a_lo = g_pts[aOff + rowStart].x;
        float a_hi = g_pts[aOff + min(rowStart + TILE - 1, nA - 1)].x;
        float b_lo = g_pts[bOff + chunkBase].x;
        float b_hi = g_pts[bOff + min(chunkBase + TILE - 1, nB - 1)].x;
        if (fmaxf(b_lo - a_hi, a_lo - b_hi) > 205.0f) return;
    }

    const int tid = threadIdx.x;
    const int wid = tid >> 5;
    int* myh = &sh[wid * NTOT];

    #pragma unroll
    for (int idx = tid; idx < NWARP * NTOT; idx += BLKT) sh[idx] = 0;

    #pragma unroll
    for (int t = 0; t < 2; t++) {
        int k = tid + t * BLKT;
        int j = chunkBase + k;
        sB[k] = (j < nB) ? g_pts[bOff + j]
                         : make_float4(0.f, 0.f, 0.f, 1e30f);
    }

    float ax2[2], ay2[2], az2[2], aw[2];
    int   irow[2];
    #pragma unroll
    for (int t = 0; t < 2; t++) {
        int i = rowStart + tid + t * BLKT;
        irow[t] = i;
        float4 a = (i < nA) ? g_pts[aOff + i]
                            : make_float4(0.f, 0.f, 0.f, 1e30f);
        ax2[t] = -2.0f * a.x; ay2[t] = -2.0f * a.y;
        az2[t] = -2.0f * a.z; aw[t]  = a.w;
    }
    __syncthreads();

    if (diag) {
        #pragma unroll 4
        for (int k = 0; k < TILE; k++) {
            float4 b = sB[k];
            #pragma unroll
            for (int t = 0; t < 2; t++) {
                float s = aw[t] + b.w;
                s = fmaf(ax2[t], b.x, s);
                s = fmaf(ay2[t], b.y, s);
                s = fmaf(az2[t], b.z, s);
                float d = fsqrt_approx(fmaxf(s, 0.0f));
                if (d < (float)NTOT && (chunkBase + k) > irow[t])
                    atomicAdd(&myh[(int)d], 1);
            }
        }
    } else {
        #pragma unroll 4
        for (int k = 0; k < TILE; k++) {
            float4 b = sB[k];
            #pragma unroll
            for (int t = 0; t < 2; t++) {
                float s = aw[t] + b.w;
                s = fmaf(ax2[t], b.x, s);
                s = fmaf(ay2[t], b.y, s);
                s = fmaf(az2[t], b.z, s);
                float d = fsqrt_approx(fmaxf(s, 0.0f));
                if (d < (float)NTOT)
                    atomicAdd(&myh[(int)d], 1);
            }
        }
    }
    __syncthreads();

    for (int t = tid; t < NTOT; t += BLKT) {
        int v = sh[t] + sh[NTOT + t] + sh[2 * NTOT + t] + sh[3 * NTOT + t];
        if (v) atomicAdd(&g_hist[histIdx * NTOT + t], v);
    }
}

// Single block: normalize all 800 outputs, then zero g_hist for next replay.
__global__ void finalize_kernel(const float* __restrict__ count_in,
                                float* __restrict__ out,
                                const float* __restrict__ rs,
                                int n0, int n1)
{
    int idx = threadIdx.x;
    if (idx < 4 * NTOT) {
        int k  = idx % NTOT;
        int ij = idx / NTOT;                       // i*2 + j
        int histIdx = (ij == 0) ? 0 : ((ij == 3) ? 2 : 1);
        float mult  = (ij == 0 || ij == 3) ? 2.0f : 1.0f;  // triangle -> full
        float na = (float)((ij >> 1) ? n1 : n0);
        float nb = (float)((ij & 1) ? n1 : n0);
        float vol = rs[0] * rs[1] * rs[2];

        float counts = (float)g_hist[histIdx * NTOT + k] * mult;
        double r = 0.025 + (double)k * 0.05;
        float sv = (float)(r * 0.05 * 2.0 * 3.14159265358979323846 * 3.0);
        float density = nb / vol;
        float res = counts / density / sv / na;   // same division order as ref
        out[idx] = count_in[idx] + res;
    }
    __syncthreads();
    if (idx < 3 * NTOT) g_hist[idx] = 0;
}

extern "C" void kernel_launch(void* const* d_in, const int* in_sizes, int n_in,
                              void* d_out, int out_size)
{
    const float* pos0  = (const float*)d_in[0];
    const float* pos1  = (const float*)d_in[1];
    const float* count = (const float*)d_in[2];
    const float* rs    = (const float*)d_in[3];
    int n0 = in_sizes[0] / 3;
    int n1 = in_sizes[1] / 3;
    float* out = (float*)d_out;

    sort_kernel<<<2, NBUCK>>>(pos0, pos1, rs, n0, n1);

    int nb0 = (n0 + TILE - 1) / TILE;
    int nb1 = (n1 + TILE - 1) / TILE;
    int T0 = nb0 * (nb0 + 1) / 2;
    int C  = nb0 * nb1;
    int T1 = nb1 * (nb1 + 1) / 2;
    pair_fused_kernel<<<T0 + C + T1, BLKT>>>(n0, n1, nb0, nb1, T0, C);

    finalize_kernel<<<1, 4 * NTOT>>>(count, out, rs, n0, n1);
}